// round 1
// baseline (speedup 1.0000x reference)
#include <cuda_runtime.h>

#define B_   256
#define S_   2048
#define F_   64
#define NP   (B_ * S_)          // 524288 (b,s) points

// ---------------- scratch (device globals; no allocations) ----------------
// px1: [2][S][B][16]  gate-permuted: slot j*4+t holds gate (t*4+j), t in {i,f,g,o}
__device__ float g_px1[2 * S_ * B_ * 16];   // 67.1 MB
// h1:  [S][B][8]      (fwd h[0..3] | bwd h[4..7])
__device__ float g_h1[S_ * B_ * 8];         // 16.8 MB
// px2: [2][S][B][8]   gate-permuted: slot j*4+t holds gate (t*2+j)
__device__ float g_px2[2 * S_ * B_ * 8];    // 33.6 MB

// ---------------- fast activations (fp32-accurate, EX2/RCP approx) --------
__device__ __forceinline__ float ex2a(float x) {
    float r; asm("ex2.approx.f32 %0, %1;" : "=f"(r) : "f"(x)); return r;
}
__device__ __forceinline__ float rcpa(float x) {
    float r; asm("rcp.approx.f32 %0, %1;" : "=f"(r) : "f"(x)); return r;
}
__device__ __forceinline__ float sigm(float x) {
    // 1/(1+exp(-x)) = 1/(1+2^(-x*log2e))
    return rcpa(1.0f + ex2a(-1.44269504088896340736f * x));
}
__device__ __forceinline__ float tanha(float x) {
    // tanh(x) = 1 - 2/(1+exp(2x)) = 1 - 2/(1+2^(x*2*log2e))
    return fmaf(-2.0f, rcpa(1.0f + ex2a(2.88539008177792681472f * x)), 1.0f);
}

// ---------------- kernel A: layer-1 input projection -----------------------
// px1[dir][s][b][j*4+t] = x[b,s,:] . Wih[t*4+j,:] + bih[t*4+j] + bhh[t*4+j]
__global__ __launch_bounds__(256) void k_px1(
    const float* __restrict__ x,
    const float* __restrict__ Wih_f, const float* __restrict__ bih_f, const float* __restrict__ bhh_f,
    const float* __restrict__ Wih_b, const float* __restrict__ bih_b, const float* __restrict__ bhh_b)
{
    __shared__ float Ws[2 * 16 * 64];
    __shared__ float bs[2 * 16];
    int t = threadIdx.x;
    for (int i = t; i < 16 * 64; i += 256) {
        Ws[i]        = Wih_f[i];
        Ws[1024 + i] = Wih_b[i];
    }
    if (t < 16) {
        bs[t]      = bih_f[t] + bhh_f[t];
        bs[16 + t] = bih_b[t] + bhh_b[t];
    }
    __syncthreads();

    int p = blockIdx.x * 256 + t;          // p = b*S + s  (s fastest -> coalesced x reads)
    int b = p >> 11;
    int s = p & (S_ - 1);

    float xr[64];
    const float4* xp = reinterpret_cast<const float4*>(x) + (size_t)p * 16;
#pragma unroll
    for (int i = 0; i < 16; ++i) {
        float4 v = xp[i];
        xr[4 * i + 0] = v.x; xr[4 * i + 1] = v.y;
        xr[4 * i + 2] = v.z; xr[4 * i + 3] = v.w;
    }

#pragma unroll 1
    for (int dir = 0; dir < 2; ++dir) {
        float acc[16];
#pragma unroll
        for (int g = 0; g < 16; ++g) {
            float a = bs[dir * 16 + g];
            const float4* wr = reinterpret_cast<const float4*>(Ws + dir * 1024 + g * 64);
#pragma unroll
            for (int q = 0; q < 16; ++q) {
                float4 w = wr[q];
                a = fmaf(xr[4 * q + 0], w.x, a);
                a = fmaf(xr[4 * q + 1], w.y, a);
                a = fmaf(xr[4 * q + 2], w.z, a);
                a = fmaf(xr[4 * q + 3], w.w, a);
            }
            acc[g] = a;
        }
        float4* o = reinterpret_cast<float4*>(g_px1) + ((size_t)(dir * S_ + s) * B_ + b) * 4;
#pragma unroll
        for (int j = 0; j < 4; ++j)
            o[j] = make_float4(acc[j], acc[4 + j], acc[8 + j], acc[12 + j]);
    }
}

// ---------------- kernel B: layer-1 recurrence (4 lanes / sequence-dir) ----
#define LSTM1_STEP(P, SIDX)                                                        \
    {                                                                              \
        float h0 = __shfl_sync(0xffffffffu, h, lb);                                \
        float h1v = __shfl_sync(0xffffffffu, h, lb + 1);                           \
        float h2v = __shfl_sync(0xffffffffu, h, lb + 2);                           \
        float h3v = __shfl_sync(0xffffffffu, h, lb + 3);                           \
        float gi = fmaf(Wi.x, h0, fmaf(Wi.y, h1v, fmaf(Wi.z, h2v, fmaf(Wi.w, h3v, (P).x)))); \
        float gf = fmaf(Wff.x, h0, fmaf(Wff.y, h1v, fmaf(Wff.z, h2v, fmaf(Wff.w, h3v, (P).y)))); \
        float gg = fmaf(Wg.x, h0, fmaf(Wg.y, h1v, fmaf(Wg.z, h2v, fmaf(Wg.w, h3v, (P).z)))); \
        float go = fmaf(Wo.x, h0, fmaf(Wo.y, h1v, fmaf(Wo.z, h2v, fmaf(Wo.w, h3v, (P).w)))); \
        gi = sigm(gi); gf = sigm(gf); gg = tanha(gg); go = sigm(go);               \
        c = fmaf(gf, c, gi * gg);                                                  \
        h = go * tanha(c);                                                         \
        hout[(size_t)(SIDX) * (B_ * 8)] = h;                                       \
    }

__global__ __launch_bounds__(32) void k_rec1(
    const float* __restrict__ Whh_f, const float* __restrict__ Whh_b)
{
    int lane = threadIdx.x;
    int dir  = blockIdx.x >> 5;                    // 0..1
    int b    = (blockIdx.x & 31) * 8 + (lane >> 2);
    int j    = lane & 3;
    int lb   = lane & ~3;

    const float* Whh = dir ? Whh_b : Whh_f;        // [16][4]
    float4 Wi  = *reinterpret_cast<const float4*>(Whh + (0  + j) * 4);
    float4 Wff = *reinterpret_cast<const float4*>(Whh + (4  + j) * 4);
    float4 Wg  = *reinterpret_cast<const float4*>(Whh + (8  + j) * 4);
    float4 Wo  = *reinterpret_cast<const float4*>(Whh + (12 + j) * 4);

    const float4* pbase = reinterpret_cast<const float4*>(g_px1)
                        + (size_t)dir * S_ * B_ * 4 + (size_t)b * 4 + j;
    float* hout = g_h1 + (size_t)b * 8 + dir * 4 + j;

    const int s0 = dir ? (S_ - 1) : 0;
    const int sg = dir ? -1 : 1;

#define PX1AT(IT) __ldg(pbase + (size_t)(s0 + sg * (IT)) * (B_ * 4))

    float h = 0.0f, c = 0.0f;
    float4 q0 = PX1AT(0), q1 = PX1AT(1), q2 = PX1AT(2), q3 = PX1AT(3);

#pragma unroll 1
    for (int it = 0; it < S_; it += 4) {
        float4 p;
        p = q0; q0 = PX1AT((it + 4 < S_) ? it + 4 : S_ - 1); LSTM1_STEP(p, s0 + sg * (it + 0));
        p = q1; q1 = PX1AT((it + 5 < S_) ? it + 5 : S_ - 1); LSTM1_STEP(p, s0 + sg * (it + 1));
        p = q2; q2 = PX1AT((it + 6 < S_) ? it + 6 : S_ - 1); LSTM1_STEP(p, s0 + sg * (it + 2));
        p = q3; q3 = PX1AT((it + 7 < S_) ? it + 7 : S_ - 1); LSTM1_STEP(p, s0 + sg * (it + 3));
    }
#undef PX1AT
}

// ---------------- kernel C: layer-2 input projection -----------------------
__global__ __launch_bounds__(256) void k_px2(
    const float* __restrict__ Wih_f, const float* __restrict__ bih_f, const float* __restrict__ bhh_f,
    const float* __restrict__ Wih_b, const float* __restrict__ bih_b, const float* __restrict__ bhh_b)
{
    __shared__ float Ws[2 * 8 * 8];
    __shared__ float bs[2 * 8];
    int t = threadIdx.x;
    if (t < 64) { Ws[t] = Wih_f[t]; Ws[64 + t] = Wih_b[t]; }
    if (t < 8)  { bs[t] = bih_f[t] + bhh_f[t]; bs[8 + t] = bih_b[t] + bhh_b[t]; }
    __syncthreads();

    int p = blockIdx.x * 256 + t;                  // p = s*B + b (b fastest)
    float hr[8];
    const float4* hp = reinterpret_cast<const float4*>(g_h1) + (size_t)p * 2;
    float4 v0 = hp[0], v1 = hp[1];
    hr[0] = v0.x; hr[1] = v0.y; hr[2] = v0.z; hr[3] = v0.w;
    hr[4] = v1.x; hr[5] = v1.y; hr[6] = v1.z; hr[7] = v1.w;

#pragma unroll
    for (int dir = 0; dir < 2; ++dir) {
        float acc[8];
#pragma unroll
        for (int g = 0; g < 8; ++g) {
            float a = bs[dir * 8 + g];
            const float* wr = Ws + dir * 64 + g * 8;
#pragma unroll
            for (int f = 0; f < 8; ++f) a = fmaf(hr[f], wr[f], a);
            acc[g] = a;
        }
        float4* o = reinterpret_cast<float4*>(g_px2) + ((size_t)dir * S_ * B_ + p) * 2;
        o[0] = make_float4(acc[0], acc[2], acc[4], acc[6]);   // lane 0 gates i0,f0,g0,o0
        o[1] = make_float4(acc[1], acc[3], acc[5], acc[7]);   // lane 1 gates i1,f1,g1,o1
    }
}

// ---------------- kernel D: layer-2 recurrence (2 lanes / sequence-dir) ----
#define LSTM2_STEP(P, SIDX)                                                        \
    {                                                                              \
        float h0 = __shfl_sync(0xffffffffu, h, lane & ~1);                         \
        float h1v = __shfl_sync(0xffffffffu, h, lane | 1);                         \
        float gi = fmaf(Wi.x, h0, fmaf(Wi.y, h1v, (P).x));                         \
        float gf = fmaf(Wff.x, h0, fmaf(Wff.y, h1v, (P).y));                       \
        float gg = fmaf(Wg.x, h0, fmaf(Wg.y, h1v, (P).z));                         \
        float go = fmaf(Wo.x, h0, fmaf(Wo.y, h1v, (P).w));                         \
        gi = sigm(gi); gf = sigm(gf); gg = tanha(gg); go = sigm(go);               \
        c = fmaf(gf, c, gi * gg);                                                  \
        h = go * tanha(c);                                                         \
        obase[(size_t)(SIDX) * 4] = h;                                             \
    }

__global__ __launch_bounds__(32) void k_rec2(
    const float* __restrict__ Whh_f, const float* __restrict__ Whh_b,
    float* __restrict__ out)
{
    int lane = threadIdx.x;
    int dir  = blockIdx.x >> 4;                    // 0..1
    int b    = (blockIdx.x & 15) * 16 + (lane >> 1);
    int j    = lane & 1;

    const float* Whh = dir ? Whh_b : Whh_f;        // [8][2]
    float2 Wi  = *reinterpret_cast<const float2*>(Whh + (0 + j) * 2);
    float2 Wff = *reinterpret_cast<const float2*>(Whh + (2 + j) * 2);
    float2 Wg  = *reinterpret_cast<const float2*>(Whh + (4 + j) * 2);
    float2 Wo  = *reinterpret_cast<const float2*>(Whh + (6 + j) * 2);

    const float4* pbase = reinterpret_cast<const float4*>(g_px2)
                        + (size_t)dir * S_ * B_ * 2 + (size_t)b * 2 + j;
    float* obase = out + (size_t)b * S_ * 4 + dir * 2 + j;

    const int s0 = dir ? (S_ - 1) : 0;
    const int sg = dir ? -1 : 1;

#define PX2AT(IT) __ldg(pbase + (size_t)(s0 + sg * (IT)) * (B_ * 2))

    float h = 0.0f, c = 0.0f;
    float4 q0 = PX2AT(0), q1 = PX2AT(1), q2 = PX2AT(2), q3 = PX2AT(3);

#pragma unroll 1
    for (int it = 0; it < S_; it += 4) {
        float4 p;
        p = q0; q0 = PX2AT((it + 4 < S_) ? it + 4 : S_ - 1); LSTM2_STEP(p, s0 + sg * (it + 0));
        p = q1; q1 = PX2AT((it + 5 < S_) ? it + 5 : S_ - 1); LSTM2_STEP(p, s0 + sg * (it + 1));
        p = q2; q2 = PX2AT((it + 6 < S_) ? it + 6 : S_ - 1); LSTM2_STEP(p, s0 + sg * (it + 2));
        p = q3; q3 = PX2AT((it + 7 < S_) ? it + 7 : S_ - 1); LSTM2_STEP(p, s0 + sg * (it + 3));
    }
#undef PX2AT
}

// ---------------- launch ---------------------------------------------------
extern "C" void kernel_launch(void* const* d_in, const int* in_sizes, int n_in,
                              void* d_out, int out_size)
{
    const float* x       = (const float*)d_in[0];
    const float* l1Wih_f = (const float*)d_in[1];
    const float* l1Whh_f = (const float*)d_in[2];
    const float* l1bih_f = (const float*)d_in[3];
    const float* l1bhh_f = (const float*)d_in[4];
    const float* l1Wih_b = (const float*)d_in[5];
    const float* l1Whh_b = (const float*)d_in[6];
    const float* l1bih_b = (const float*)d_in[7];
    const float* l1bhh_b = (const float*)d_in[8];
    const float* l2Wih_f = (const float*)d_in[9];
    const float* l2Whh_f = (const float*)d_in[10];
    const float* l2bih_f = (const float*)d_in[11];
    const float* l2bhh_f = (const float*)d_in[12];
    const float* l2Wih_b = (const float*)d_in[13];
    const float* l2Whh_b = (const float*)d_in[14];
    const float* l2bih_b = (const float*)d_in[15];
    const float* l2bhh_b = (const float*)d_in[16];

    k_px1<<<NP / 256, 256>>>(x, l1Wih_f, l1bih_f, l1bhh_f, l1Wih_b, l1bih_b, l1bhh_b);
    k_rec1<<<64, 32>>>(l1Whh_f, l1Whh_b);
    k_px2<<<NP / 256, 256>>>(l2Wih_f, l2bih_f, l2bhh_f, l2Wih_b, l2bih_b, l2bhh_b);
    k_rec2<<<32, 32>>>(l2Whh_f, l2Whh_b, (float*)d_out);
}

// round 2
// speedup vs baseline: 1.3813x; 1.3813x over previous
#include <cuda_runtime.h>

#define B_   256
#define S_   2048
#define F_   64
#define NP   (B_ * S_)          // 524288 (b,s) points

// ---------------- scratch (device globals; no allocations) ----------------
// px1: [2][S][B][16]  gate-permuted: slot j*4+t holds gate (t*4+j), t in {i,f,g,o}
__device__ float g_px1[2 * S_ * B_ * 16];   // 67.1 MB
// h1:  [S][B][8]      (fwd h[0..3] | bwd h[4..7])
__device__ float g_h1[S_ * B_ * 8];         // 16.8 MB
// px2: [2][S][B][8]   gate-permuted: slot j*4+t holds gate (t*2+j)
__device__ float g_px2[2 * S_ * B_ * 8];    // 33.6 MB

// ---------------- fast activations (MUFU.TANH single-instruction) ---------
__device__ __forceinline__ float tanha(float x) {
    float r; asm("tanh.approx.f32 %0, %1;" : "=f"(r) : "f"(x)); return r;
}
__device__ __forceinline__ float sigm(float x) {
    // sigmoid(x) = 0.5*tanh(0.5x) + 0.5   (MUL + MUFU.TANH + FMA, ~24 cyc)
    return fmaf(0.5f, tanha(0.5f * x), 0.5f);
}

// ---------------- kernel A: layer-1 input projection -----------------------
// px1[dir][s][b][j*4+t] = x[b,s,:] . Wih[t*4+j,:] + bih[t*4+j] + bhh[t*4+j]
__global__ __launch_bounds__(256) void k_px1(
    const float* __restrict__ x,
    const float* __restrict__ Wih_f, const float* __restrict__ bih_f, const float* __restrict__ bhh_f,
    const float* __restrict__ Wih_b, const float* __restrict__ bih_b, const float* __restrict__ bhh_b)
{
    __shared__ float Ws[2 * 16 * 64];
    __shared__ float bs[2 * 16];
    int t = threadIdx.x;
    for (int i = t; i < 16 * 64; i += 256) {
        Ws[i]        = Wih_f[i];
        Ws[1024 + i] = Wih_b[i];
    }
    if (t < 16) {
        bs[t]      = bih_f[t] + bhh_f[t];
        bs[16 + t] = bih_b[t] + bhh_b[t];
    }
    __syncthreads();

    int p = blockIdx.x * 256 + t;          // p = b*S + s  (s fastest -> coalesced x reads)
    int b = p >> 11;
    int s = p & (S_ - 1);

    float xr[64];
    const float4* xp = reinterpret_cast<const float4*>(x) + (size_t)p * 16;
#pragma unroll
    for (int i = 0; i < 16; ++i) {
        float4 v = xp[i];
        xr[4 * i + 0] = v.x; xr[4 * i + 1] = v.y;
        xr[4 * i + 2] = v.z; xr[4 * i + 3] = v.w;
    }

#pragma unroll 1
    for (int dir = 0; dir < 2; ++dir) {
        float acc[16];
#pragma unroll
        for (int g = 0; g < 16; ++g) {
            float a = bs[dir * 16 + g];
            const float4* wr = reinterpret_cast<const float4*>(Ws + dir * 1024 + g * 64);
#pragma unroll
            for (int q = 0; q < 16; ++q) {
                float4 w = wr[q];
                a = fmaf(xr[4 * q + 0], w.x, a);
                a = fmaf(xr[4 * q + 1], w.y, a);
                a = fmaf(xr[4 * q + 2], w.z, a);
                a = fmaf(xr[4 * q + 3], w.w, a);
            }
            acc[g] = a;
        }
        float4* o = reinterpret_cast<float4*>(g_px1) + ((size_t)(dir * S_ + s) * B_ + b) * 4;
#pragma unroll
        for (int j = 0; j < 4; ++j)
            o[j] = make_float4(acc[j], acc[4 + j], acc[8 + j], acc[12 + j]);
    }
}

// ---------------- kernel B: layer-1 recurrence (4 lanes / sequence-dir) ----
#define LSTM1_STEP(P, SIDX)                                                        \
    {                                                                              \
        float h0 = __shfl_sync(0xffffffffu, h, lb);                                \
        float h1v = __shfl_sync(0xffffffffu, h, lb + 1);                           \
        float h2v = __shfl_sync(0xffffffffu, h, lb + 2);                           \
        float h3v = __shfl_sync(0xffffffffu, h, lb + 3);                           \
        float gi = fmaf(Wi.x, h0, fmaf(Wi.y, h1v, fmaf(Wi.z, h2v, fmaf(Wi.w, h3v, (P).x)))); \
        float gf = fmaf(Wff.x, h0, fmaf(Wff.y, h1v, fmaf(Wff.z, h2v, fmaf(Wff.w, h3v, (P).y)))); \
        float gg = fmaf(Wg.x, h0, fmaf(Wg.y, h1v, fmaf(Wg.z, h2v, fmaf(Wg.w, h3v, (P).z)))); \
        float go = fmaf(Wo.x, h0, fmaf(Wo.y, h1v, fmaf(Wo.z, h2v, fmaf(Wo.w, h3v, (P).w)))); \
        gi = sigm(gi); gf = sigm(gf); gg = tanha(gg); go = sigm(go);               \
        c = fmaf(gf, c, gi * gg);                                                  \
        h = go * tanha(c);                                                         \
        hout[(size_t)(SIDX) * (B_ * 8)] = h;                                       \
    }

__global__ __launch_bounds__(32) void k_rec1(
    const float* __restrict__ Whh_f, const float* __restrict__ Whh_b)
{
    int lane = threadIdx.x;
    int dir  = blockIdx.x >> 5;                    // 0..1
    int b    = (blockIdx.x & 31) * 8 + (lane >> 2);
    int j    = lane & 3;
    int lb   = lane & ~3;

    const float* Whh = dir ? Whh_b : Whh_f;        // [16][4]
    float4 Wi  = *reinterpret_cast<const float4*>(Whh + (0  + j) * 4);
    float4 Wff = *reinterpret_cast<const float4*>(Whh + (4  + j) * 4);
    float4 Wg  = *reinterpret_cast<const float4*>(Whh + (8  + j) * 4);
    float4 Wo  = *reinterpret_cast<const float4*>(Whh + (12 + j) * 4);

    const float4* pbase = reinterpret_cast<const float4*>(g_px1)
                        + (size_t)dir * S_ * B_ * 4 + (size_t)b * 4 + j;
    float* hout = g_h1 + (size_t)b * 8 + dir * 4 + j;

    const int s0 = dir ? (S_ - 1) : 0;
    const int sg = dir ? -1 : 1;

#define PX1AT(IT) __ldg(pbase + (size_t)(s0 + sg * (IT)) * (B_ * 4))

    float h = 0.0f, c = 0.0f;
    float4 q0 = PX1AT(0), q1 = PX1AT(1), q2 = PX1AT(2), q3 = PX1AT(3);

#pragma unroll 1
    for (int it = 0; it < S_; it += 4) {
        float4 p;
        p = q0; q0 = PX1AT(min(it + 4, S_ - 1)); LSTM1_STEP(p, s0 + sg * (it + 0));
        p = q1; q1 = PX1AT(min(it + 5, S_ - 1)); LSTM1_STEP(p, s0 + sg * (it + 1));
        p = q2; q2 = PX1AT(min(it + 6, S_ - 1)); LSTM1_STEP(p, s0 + sg * (it + 2));
        p = q3; q3 = PX1AT(min(it + 7, S_ - 1)); LSTM1_STEP(p, s0 + sg * (it + 3));
    }
#undef PX1AT
}

// ---------------- kernel C: layer-2 input projection -----------------------
__global__ __launch_bounds__(256) void k_px2(
    const float* __restrict__ Wih_f, const float* __restrict__ bih_f, const float* __restrict__ bhh_f,
    const float* __restrict__ Wih_b, const float* __restrict__ bih_b, const float* __restrict__ bhh_b)
{
    __shared__ float Ws[2 * 8 * 8];
    __shared__ float bs[2 * 8];
    int t = threadIdx.x;
    if (t < 64) { Ws[t] = Wih_f[t]; Ws[64 + t] = Wih_b[t]; }
    if (t < 8)  { bs[t] = bih_f[t] + bhh_f[t]; bs[8 + t] = bih_b[t] + bhh_b[t]; }
    __syncthreads();

    int p = blockIdx.x * 256 + t;                  // p = s*B + b (b fastest)
    float hr[8];
    const float4* hp = reinterpret_cast<const float4*>(g_h1) + (size_t)p * 2;
    float4 v0 = hp[0], v1 = hp[1];
    hr[0] = v0.x; hr[1] = v0.y; hr[2] = v0.z; hr[3] = v0.w;
    hr[4] = v1.x; hr[5] = v1.y; hr[6] = v1.z; hr[7] = v1.w;

#pragma unroll
    for (int dir = 0; dir < 2; ++dir) {
        float acc[8];
#pragma unroll
        for (int g = 0; g < 8; ++g) {
            float a = bs[dir * 8 + g];
            const float* wr = Ws + dir * 64 + g * 8;
#pragma unroll
            for (int f = 0; f < 8; ++f) a = fmaf(hr[f], wr[f], a);
            acc[g] = a;
        }
        float4* o = reinterpret_cast<float4*>(g_px2) + ((size_t)dir * S_ * B_ + p) * 2;
        o[0] = make_float4(acc[0], acc[2], acc[4], acc[6]);   // lane 0 gates i0,f0,g0,o0
        o[1] = make_float4(acc[1], acc[3], acc[5], acc[7]);   // lane 1 gates i1,f1,g1,o1
    }
}

// ---------------- kernel D: layer-2 recurrence (2 lanes / sequence-dir) ----
#define LSTM2_STEP(P, SIDX)                                                        \
    {                                                                              \
        float h0 = __shfl_sync(0xffffffffu, h, lane & ~1);                         \
        float h1v = __shfl_sync(0xffffffffu, h, lane | 1);                         \
        float gi = fmaf(Wi.x, h0, fmaf(Wi.y, h1v, (P).x));                         \
        float gf = fmaf(Wff.x, h0, fmaf(Wff.y, h1v, (P).y));                       \
        float gg = fmaf(Wg.x, h0, fmaf(Wg.y, h1v, (P).z));                         \
        float go = fmaf(Wo.x, h0, fmaf(Wo.y, h1v, (P).w));                         \
        gi = sigm(gi); gf = sigm(gf); gg = tanha(gg); go = sigm(go);               \
        c = fmaf(gf, c, gi * gg);                                                  \
        h = go * tanha(c);                                                         \
        obase[(size_t)(SIDX) * 4] = h;                                             \
    }

__global__ __launch_bounds__(32) void k_rec2(
    const float* __restrict__ Whh_f, const float* __restrict__ Whh_b,
    float* __restrict__ out)
{
    int lane = threadIdx.x;
    int dir  = blockIdx.x >> 4;                    // 0..1
    int b    = (blockIdx.x & 15) * 16 + (lane >> 1);
    int j    = lane & 1;

    const float* Whh = dir ? Whh_b : Whh_f;        // [8][2]
    float2 Wi  = *reinterpret_cast<const float2*>(Whh + (0 + j) * 2);
    float2 Wff = *reinterpret_cast<const float2*>(Whh + (2 + j) * 2);
    float2 Wg  = *reinterpret_cast<const float2*>(Whh + (4 + j) * 2);
    float2 Wo  = *reinterpret_cast<const float2*>(Whh + (6 + j) * 2);

    const float4* pbase = reinterpret_cast<const float4*>(g_px2)
                        + (size_t)dir * S_ * B_ * 2 + (size_t)b * 2 + j;
    float* obase = out + (size_t)b * S_ * 4 + dir * 2 + j;

    const int s0 = dir ? (S_ - 1) : 0;
    const int sg = dir ? -1 : 1;

#define PX2AT(IT) __ldg(pbase + (size_t)(s0 + sg * (IT)) * (B_ * 2))

    float h = 0.0f, c = 0.0f;
    float4 q0 = PX2AT(0), q1 = PX2AT(1), q2 = PX2AT(2), q3 = PX2AT(3);

#pragma unroll 1
    for (int it = 0; it < S_; it += 4) {
        float4 p;
        p = q0; q0 = PX2AT(min(it + 4, S_ - 1)); LSTM2_STEP(p, s0 + sg * (it + 0));
        p = q1; q1 = PX2AT(min(it + 5, S_ - 1)); LSTM2_STEP(p, s0 + sg * (it + 1));
        p = q2; q2 = PX2AT(min(it + 6, S_ - 1)); LSTM2_STEP(p, s0 + sg * (it + 2));
        p = q3; q3 = PX2AT(min(it + 7, S_ - 1)); LSTM2_STEP(p, s0 + sg * (it + 3));
    }
#undef PX2AT
}

// ---------------- launch ---------------------------------------------------
extern "C" void kernel_launch(void* const* d_in, const int* in_sizes, int n_in,
                              void* d_out, int out_size)
{
    const float* x       = (const float*)d_in[0];
    const float* l1Wih_f = (const float*)d_in[1];
    const float* l1Whh_f = (const float*)d_in[2];
    const float* l1bih_f = (const float*)d_in[3];
    const float* l1bhh_f = (const float*)d_in[4];
    const float* l1Wih_b = (const float*)d_in[5];
    const float* l1Whh_b = (const float*)d_in[6];
    const float* l1bih_b = (const float*)d_in[7];
    const float* l1bhh_b = (const float*)d_in[8];
    const float* l2Wih_f = (const float*)d_in[9];
    const float* l2Whh_f = (const float*)d_in[10];
    const float* l2bih_f = (const float*)d_in[11];
    const float* l2bhh_f = (const float*)d_in[12];
    const float* l2Wih_b = (const float*)d_in[13];
    const float* l2Whh_b = (const float*)d_in[14];
    const float* l2bih_b = (const float*)d_in[15];
    const float* l2bhh_b = (const float*)d_in[16];

    k_px1<<<NP / 256, 256>>>(x, l1Wih_f, l1bih_f, l1bhh_f, l1Wih_b, l1bih_b, l1bhh_b);
    k_rec1<<<64, 32>>>(l1Whh_f, l1Whh_b);
    k_px2<<<NP / 256, 256>>>(l2Wih_f, l2bih_f, l2bhh_f, l2Wih_b, l2bih_b, l2bhh_b);
    k_rec2<<<32, 32>>>(l2Whh_f, l2Whh_b, (float*)d_out);
}

// round 3
// speedup vs baseline: 1.5134x; 1.0957x over previous
#include <cuda_runtime.h>

#define B_   256
#define S_   2048
#define F_   64
#define NP   (B_ * S_)          // 524288 (b,s) points

// ---------------- scratch (device globals; no allocations) ----------------
// px1: [2][S][B][16]  gate-permuted: slot j*4+t holds gate (t*4+j), t in {i,f,g,o}
__device__ float g_px1[2 * S_ * B_ * 16];   // 67.1 MB
// h1:  [S][B][8]      (fwd h[0..3] | bwd h[4..7])
__device__ float g_h1[S_ * B_ * 8];         // 16.8 MB
// px2: [2][S][B][2 float4s] : [i0,f0,g0,o0][i1,f1,g1,o1]
__device__ float g_px2[2 * S_ * B_ * 8];    // 33.6 MB

// ---------------- fast activations (MUFU.TANH single-instruction) ---------
__device__ __forceinline__ float tanha(float x) {
    float r; asm("tanh.approx.f32 %0, %1;" : "=f"(r) : "f"(x)); return r;
}
__device__ __forceinline__ float sigm(float x) {
    return fmaf(0.5f, tanha(0.5f * x), 0.5f);
}

// ---------------- kernel A: layer-1 input projection -----------------------
__global__ __launch_bounds__(256) void k_px1(
    const float* __restrict__ x,
    const float* __restrict__ Wih_f, const float* __restrict__ bih_f, const float* __restrict__ bhh_f,
    const float* __restrict__ Wih_b, const float* __restrict__ bih_b, const float* __restrict__ bhh_b)
{
    __shared__ float Ws[2 * 16 * 64];
    __shared__ float bs[2 * 16];
    int t = threadIdx.x;
    for (int i = t; i < 16 * 64; i += 256) {
        Ws[i]        = Wih_f[i];
        Ws[1024 + i] = Wih_b[i];
    }
    if (t < 16) {
        bs[t]      = bih_f[t] + bhh_f[t];
        bs[16 + t] = bih_b[t] + bhh_b[t];
    }
    __syncthreads();

    int p = blockIdx.x * 256 + t;          // p = b*S + s
    int b = p >> 11;
    int s = p & (S_ - 1);

    float xr[64];
    const float4* xp = reinterpret_cast<const float4*>(x) + (size_t)p * 16;
#pragma unroll
    for (int i = 0; i < 16; ++i) {
        float4 v = xp[i];
        xr[4 * i + 0] = v.x; xr[4 * i + 1] = v.y;
        xr[4 * i + 2] = v.z; xr[4 * i + 3] = v.w;
    }

#pragma unroll 1
    for (int dir = 0; dir < 2; ++dir) {
        float acc[16];
#pragma unroll
        for (int g = 0; g < 16; ++g) {
            float a = bs[dir * 16 + g];
            const float4* wr = reinterpret_cast<const float4*>(Ws + dir * 1024 + g * 64);
#pragma unroll
            for (int q = 0; q < 16; ++q) {
                float4 w = wr[q];
                a = fmaf(xr[4 * q + 0], w.x, a);
                a = fmaf(xr[4 * q + 1], w.y, a);
                a = fmaf(xr[4 * q + 2], w.z, a);
                a = fmaf(xr[4 * q + 3], w.w, a);
            }
            acc[g] = a;
        }
        float4* o = reinterpret_cast<float4*>(g_px1) + ((size_t)(dir * S_ + s) * B_ + b) * 4;
#pragma unroll
        for (int j = 0; j < 4; ++j)
            o[j] = make_float4(acc[j], acc[4 + j], acc[8 + j], acc[12 + j]);
    }
}

// ---------------- kernel B: layer-1 recurrence (4 lanes/seq, 3 shuffles) ---
// Weights per lane are permuted to shuffle-arrival order:
//   W.x -> own h (no shuffle), W.y -> h[(j+1)&3], W.z -> h[(j+2)&3], W.w -> h[(j+3)&3]
#define LSTM1_STEP(P, SIDX)                                                        \
    {                                                                              \
        float hn1 = __shfl_sync(0xffffffffu, h, src1);                             \
        float hn2 = __shfl_sync(0xffffffffu, h, src2);                             \
        float hn3 = __shfl_sync(0xffffffffu, h, src3);                             \
        float gi = fmaf(Wi.w, hn3, fmaf(Wi.z, hn2, fmaf(Wi.y, hn1, fmaf(Wi.x, h, (P).x)))); \
        float gf = fmaf(Wff.w, hn3, fmaf(Wff.z, hn2, fmaf(Wff.y, hn1, fmaf(Wff.x, h, (P).y)))); \
        float gg = fmaf(Wg.w, hn3, fmaf(Wg.z, hn2, fmaf(Wg.y, hn1, fmaf(Wg.x, h, (P).z)))); \
        float go = fmaf(Wo.w, hn3, fmaf(Wo.z, hn2, fmaf(Wo.y, hn1, fmaf(Wo.x, h, (P).w)))); \
        gi = sigm(gi); gf = sigm(gf); gg = tanha(gg); go = sigm(go);               \
        c = fmaf(gf, c, gi * gg);                                                  \
        h = go * tanha(c);                                                         \
        hout[(size_t)(SIDX) * (B_ * 8)] = h;                                       \
    }

__global__ __launch_bounds__(32) void k_rec1(
    const float* __restrict__ Whh_f, const float* __restrict__ Whh_b)
{
    int lane = threadIdx.x;
    int dir  = blockIdx.x >> 5;                    // 0..1
    int b    = (blockIdx.x & 31) * 8 + (lane >> 2);
    int j    = lane & 3;
    int lb   = lane & ~3;
    int j1 = (j + 1) & 3, j2 = (j + 2) & 3, j3 = (j + 3) & 3;
    int src1 = lb + j1, src2 = lb + j2, src3 = lb + j3;

    const float* Whh = dir ? Whh_b : Whh_f;        // [16][4]
    // permuted weight loads: component order (own, +1, +2, +3)
    float4 Wi  = make_float4(Whh[(0  + j) * 4 + j], Whh[(0  + j) * 4 + j1],
                             Whh[(0  + j) * 4 + j2], Whh[(0  + j) * 4 + j3]);
    float4 Wff = make_float4(Whh[(4  + j) * 4 + j], Whh[(4  + j) * 4 + j1],
                             Whh[(4  + j) * 4 + j2], Whh[(4  + j) * 4 + j3]);
    float4 Wg  = make_float4(Whh[(8  + j) * 4 + j], Whh[(8  + j) * 4 + j1],
                             Whh[(8  + j) * 4 + j2], Whh[(8  + j) * 4 + j3]);
    float4 Wo  = make_float4(Whh[(12 + j) * 4 + j], Whh[(12 + j) * 4 + j1],
                             Whh[(12 + j) * 4 + j2], Whh[(12 + j) * 4 + j3]);

    const float4* pbase = reinterpret_cast<const float4*>(g_px1)
                        + (size_t)dir * S_ * B_ * 4 + (size_t)b * 4 + j;
    float* hout = g_h1 + (size_t)b * 8 + dir * 4 + j;

    const int s0 = dir ? (S_ - 1) : 0;
    const int sg = dir ? -1 : 1;

#define PX1AT(IT) __ldg(pbase + (size_t)(s0 + sg * (IT)) * (B_ * 4))

    float h = 0.0f, c = 0.0f;
    float4 q[8];
#pragma unroll
    for (int k = 0; k < 8; ++k) q[k] = PX1AT(k);

#pragma unroll 1
    for (int it = 0; it < S_; it += 8) {
        float4 p;
        p = q[0]; q[0] = PX1AT(min(it +  8, S_ - 1)); LSTM1_STEP(p, s0 + sg * (it + 0));
        p = q[1]; q[1] = PX1AT(min(it +  9, S_ - 1)); LSTM1_STEP(p, s0 + sg * (it + 1));
        p = q[2]; q[2] = PX1AT(min(it + 10, S_ - 1)); LSTM1_STEP(p, s0 + sg * (it + 2));
        p = q[3]; q[3] = PX1AT(min(it + 11, S_ - 1)); LSTM1_STEP(p, s0 + sg * (it + 3));
        p = q[4]; q[4] = PX1AT(min(it + 12, S_ - 1)); LSTM1_STEP(p, s0 + sg * (it + 4));
        p = q[5]; q[5] = PX1AT(min(it + 13, S_ - 1)); LSTM1_STEP(p, s0 + sg * (it + 5));
        p = q[6]; q[6] = PX1AT(min(it + 14, S_ - 1)); LSTM1_STEP(p, s0 + sg * (it + 6));
        p = q[7]; q[7] = PX1AT(min(it + 15, S_ - 1)); LSTM1_STEP(p, s0 + sg * (it + 7));
    }
#undef PX1AT
}

// ---------------- kernel C: layer-2 input projection -----------------------
__global__ __launch_bounds__(256) void k_px2(
    const float* __restrict__ Wih_f, const float* __restrict__ bih_f, const float* __restrict__ bhh_f,
    const float* __restrict__ Wih_b, const float* __restrict__ bih_b, const float* __restrict__ bhh_b)
{
    __shared__ float Ws[2 * 8 * 8];
    __shared__ float bs[2 * 8];
    int t = threadIdx.x;
    if (t < 64) { Ws[t] = Wih_f[t]; Ws[64 + t] = Wih_b[t]; }
    if (t < 8)  { bs[t] = bih_f[t] + bhh_f[t]; bs[8 + t] = bih_b[t] + bhh_b[t]; }
    __syncthreads();

    int p = blockIdx.x * 256 + t;                  // p = s*B + b (b fastest)
    float hr[8];
    const float4* hp = reinterpret_cast<const float4*>(g_h1) + (size_t)p * 2;
    float4 v0 = hp[0], v1 = hp[1];
    hr[0] = v0.x; hr[1] = v0.y; hr[2] = v0.z; hr[3] = v0.w;
    hr[4] = v1.x; hr[5] = v1.y; hr[6] = v1.z; hr[7] = v1.w;

#pragma unroll
    for (int dir = 0; dir < 2; ++dir) {
        float acc[8];
#pragma unroll
        for (int g = 0; g < 8; ++g) {
            float a = bs[dir * 8 + g];
            const float* wr = Ws + dir * 64 + g * 8;
#pragma unroll
            for (int f = 0; f < 8; ++f) a = fmaf(hr[f], wr[f], a);
            acc[g] = a;
        }
        float4* o = reinterpret_cast<float4*>(g_px2) + ((size_t)dir * S_ * B_ + p) * 2;
        o[0] = make_float4(acc[0], acc[2], acc[4], acc[6]);   // (i0,f0,g0,o0)
        o[1] = make_float4(acc[1], acc[3], acc[5], acc[7]);   // (i1,f1,g1,o1)
    }
}

// ---------------- kernel D: layer-2 recurrence (redundant state, NO shfl) --
// Each lane owns one (b, dir): full h0,h1,c0,c1 in registers. 8 gates/lane.
#define LSTM2_STEP(PA, PB, SIDX)                                                   \
    {                                                                              \
        float i0 = sigm (fmaf(wi.y, h1, fmaf(wi.x, h0, (PA).x)));                  \
        float f0 = sigm (fmaf(wf.y, h1, fmaf(wf.x, h0, (PA).y)));                  \
        float g0 = tanha(fmaf(wg.y, h1, fmaf(wg.x, h0, (PA).z)));                  \
        float o0 = sigm (fmaf(wo.y, h1, fmaf(wo.x, h0, (PA).w)));                  \
        float i1 = sigm (fmaf(wi.w, h1, fmaf(wi.z, h0, (PB).x)));                  \
        float f1 = sigm (fmaf(wf.w, h1, fmaf(wf.z, h0, (PB).y)));                  \
        float g1 = tanha(fmaf(wg.w, h1, fmaf(wg.z, h0, (PB).z)));                  \
        float o1 = sigm (fmaf(wo.w, h1, fmaf(wo.z, h0, (PB).w)));                  \
        c0 = fmaf(f0, c0, i0 * g0);                                                \
        c1 = fmaf(f1, c1, i1 * g1);                                                \
        h0 = o0 * tanha(c0);                                                       \
        h1 = o1 * tanha(c1);                                                       \
        *reinterpret_cast<float2*>(obase + (size_t)(SIDX) * 4) = make_float2(h0, h1); \
    }

__global__ __launch_bounds__(16) void k_rec2(
    const float* __restrict__ Whh_f, const float* __restrict__ Whh_b,
    float* __restrict__ out)
{
    int lane = threadIdx.x;                        // 0..15
    int dir  = blockIdx.x >> 4;                    // 0..1
    int b    = (blockIdx.x & 15) * 16 + lane;

    const float* Whh = dir ? Whh_b : Whh_f;        // [8][2] rows: i0,i1,f0,f1,g0,g1,o0,o1
    float4 wi = *reinterpret_cast<const float4*>(Whh + 0);   // (i0.x,i0.y,i1.x,i1.y)
    float4 wf = *reinterpret_cast<const float4*>(Whh + 4);
    float4 wg = *reinterpret_cast<const float4*>(Whh + 8);
    float4 wo = *reinterpret_cast<const float4*>(Whh + 12);

    const float4* pbase = reinterpret_cast<const float4*>(g_px2)
                        + (size_t)dir * S_ * B_ * 2 + (size_t)b * 2;
    float* obase = out + (size_t)b * S_ * 4 + dir * 2;

    const int s0 = dir ? (S_ - 1) : 0;
    const int sg = dir ? -1 : 1;

#define PX2A(IT) __ldg(pbase + (size_t)(s0 + sg * (IT)) * (B_ * 2))
#define PX2B(IT) __ldg(pbase + (size_t)(s0 + sg * (IT)) * (B_ * 2) + 1)

    float h0 = 0.0f, h1 = 0.0f, c0 = 0.0f, c1 = 0.0f;
    float4 qa[8], qb[8];
#pragma unroll
    for (int k = 0; k < 8; ++k) { qa[k] = PX2A(k); qb[k] = PX2B(k); }

#pragma unroll 1
    for (int it = 0; it < S_; it += 8) {
        float4 pa, pb;
#pragma unroll
        for (int k = 0; k < 8; ++k) {
            pa = qa[k]; pb = qb[k];
            int nx = min(it + 8 + k, S_ - 1);
            qa[k] = PX2A(nx); qb[k] = PX2B(nx);
            LSTM2_STEP(pa, pb, s0 + sg * (it + k));
        }
    }
#undef PX2A
#undef PX2B
}

// ---------------- launch ---------------------------------------------------
extern "C" void kernel_launch(void* const* d_in, const int* in_sizes, int n_in,
                              void* d_out, int out_size)
{
    const float* x       = (const float*)d_in[0];
    const float* l1Wih_f = (const float*)d_in[1];
    const float* l1Whh_f = (const float*)d_in[2];
    const float* l1bih_f = (const float*)d_in[3];
    const float* l1bhh_f = (const float*)d_in[4];
    const float* l1Wih_b = (const float*)d_in[5];
    const float* l1Whh_b = (const float*)d_in[6];
    const float* l1bih_b = (const float*)d_in[7];
    const float* l1bhh_b = (const float*)d_in[8];
    const float* l2Wih_f = (const float*)d_in[9];
    const float* l2Whh_f = (const float*)d_in[10];
    const float* l2bih_f = (const float*)d_in[11];
    const float* l2bhh_f = (const float*)d_in[12];
    const float* l2Wih_b = (const float*)d_in[13];
    const float* l2Whh_b = (const float*)d_in[14];
    const float* l2bih_b = (const float*)d_in[15];
    const float* l2bhh_b = (const float*)d_in[16];

    k_px1<<<NP / 256, 256>>>(x, l1Wih_f, l1bih_f, l1bhh_f, l1Wih_b, l1bih_b, l1bhh_b);
    k_rec1<<<64, 32>>>(l1Whh_f, l1Whh_b);
    k_px2<<<NP / 256, 256>>>(l2Wih_f, l2bih_f, l2bhh_f, l2Wih_b, l2bih_b, l2bhh_b);
    k_rec2<<<32, 16>>>(l2Whh_f, l2Whh_b, (float*)d_out);
}

// round 4
// speedup vs baseline: 1.6424x; 1.0852x over previous
#include <cuda_runtime.h>

#define B_   256
#define S_   2048
#define F_   64
#define NP   (B_ * S_)
#define SP   (S_ + 32)          // padded rows (16 each side)

// ---------------- scratch (device globals; zero-init, no allocations) -----
// px1: [2][SP][B][16]  row r=16+s ; gate-permuted per lane j: (i_j,f_j,g_j,o_j)
__device__ float g_px1[2 * SP * B_ * 16];   // 68.2 MB
// h1:  [S][B][8]       (fwd h[0..3] | bwd h[4..7])
__device__ float g_h1[S_ * B_ * 8];         // 16.8 MB
// px2: [2][SP][B][8]   row r=16+s ; [i0,f0,g0,o0][i1,f1,g1,o1]
__device__ float g_px2[2 * SP * B_ * 8];    // 34.1 MB

// ---------------- activations ----------------------------------------------
__device__ __forceinline__ float tanha(float x) {
    float r; asm("tanh.approx.f32 %0, %1;" : "=f"(r) : "f"(x)); return r;
}
// pre-activation y is ALREADY scaled by 0.5 (folded into W/b)
__device__ __forceinline__ float sigm_pre(float y) {
    return fmaf(0.5f, tanha(y), 0.5f);
}

// ---------------- kernel A: layer-1 input projection ------------------------
// i/f/o rows pre-scaled by 0.5; g rows full scale.
__global__ __launch_bounds__(256) void k_px1(
    const float* __restrict__ x,
    const float* __restrict__ Wih_f, const float* __restrict__ bih_f, const float* __restrict__ bhh_f,
    const float* __restrict__ Wih_b, const float* __restrict__ bih_b, const float* __restrict__ bhh_b)
{
    __shared__ float Ws[2 * 16 * 64];
    __shared__ float bs[2 * 16];
    int t = threadIdx.x;
    for (int i = t; i < 16 * 64; i += 256) {
        int row = i >> 6;                       // 0..15 : i(0-3) f(4-7) g(8-11) o(12-15)
        float sc = (row >= 8 && row < 12) ? 1.0f : 0.5f;
        Ws[i]        = Wih_f[i] * sc;
        Ws[1024 + i] = Wih_b[i] * sc;
    }
    if (t < 16) {
        float sc = (t >= 8 && t < 12) ? 1.0f : 0.5f;
        bs[t]      = (bih_f[t] + bhh_f[t]) * sc;
        bs[16 + t] = (bih_b[t] + bhh_b[t]) * sc;
    }
    __syncthreads();

    int p = blockIdx.x * 256 + t;          // p = b*S + s
    int b = p >> 11;
    int s = p & (S_ - 1);

    float xr[64];
    const float4* xp = reinterpret_cast<const float4*>(x) + (size_t)p * 16;
#pragma unroll
    for (int i = 0; i < 16; ++i) {
        float4 v = xp[i];
        xr[4 * i + 0] = v.x; xr[4 * i + 1] = v.y;
        xr[4 * i + 2] = v.z; xr[4 * i + 3] = v.w;
    }

#pragma unroll 1
    for (int dir = 0; dir < 2; ++dir) {
        float acc[16];
#pragma unroll
        for (int g = 0; g < 16; ++g) {
            float a = bs[dir * 16 + g];
            const float4* wr = reinterpret_cast<const float4*>(Ws + dir * 1024 + g * 64);
#pragma unroll
            for (int q = 0; q < 16; ++q) {
                float4 w = wr[q];
                a = fmaf(xr[4 * q + 0], w.x, a);
                a = fmaf(xr[4 * q + 1], w.y, a);
                a = fmaf(xr[4 * q + 2], w.z, a);
                a = fmaf(xr[4 * q + 3], w.w, a);
            }
            acc[g] = a;
        }
        float4* o = reinterpret_cast<float4*>(g_px1)
                  + ((size_t)(dir * SP + 16 + s) * B_ + b) * 4;
#pragma unroll
        for (int j = 0; j < 4; ++j)
            o[j] = make_float4(acc[j], acc[4 + j], acc[8 + j], acc[12 + j]);
    }
}

// ---------------- kernel B: layer-1 recurrence ------------------------------
template <int SG>
__device__ __forceinline__ void rec1_dir(const float* __restrict__ Whh, int lane)
{
    constexpr int ROW  = B_ * 4;           // px1 row stride in float4
    constexpr int HROW = B_ * 8;           // h1 row stride in floats
    const int dir = (SG < 0);
    const int s0  = (SG < 0) ? (S_ - 1) : 0;

    int bq = (blockIdx.x & 31) * 8 + (lane >> 2);
    int j  = lane & 3;
    int lb = lane & ~3;
    int j1 = (j + 1) & 3, j2 = (j + 2) & 3, j3 = (j + 3) & 3;
    int src1 = lb + j1, src2 = lb + j2, src3 = lb + j3;

    // permuted weights, i/f/o pre-scaled by 0.5
    float4 Wi  = make_float4(Whh[(0  + j) * 4 + j]  * 0.5f, Whh[(0  + j) * 4 + j1] * 0.5f,
                             Whh[(0  + j) * 4 + j2] * 0.5f, Whh[(0  + j) * 4 + j3] * 0.5f);
    float4 Wff = make_float4(Whh[(4  + j) * 4 + j]  * 0.5f, Whh[(4  + j) * 4 + j1] * 0.5f,
                             Whh[(4  + j) * 4 + j2] * 0.5f, Whh[(4  + j) * 4 + j3] * 0.5f);
    float4 Wg  = make_float4(Whh[(8  + j) * 4 + j],         Whh[(8  + j) * 4 + j1],
                             Whh[(8  + j) * 4 + j2],        Whh[(8  + j) * 4 + j3]);
    float4 Wo  = make_float4(Whh[(12 + j) * 4 + j]  * 0.5f, Whh[(12 + j) * 4 + j1] * 0.5f,
                             Whh[(12 + j) * 4 + j2] * 0.5f, Whh[(12 + j) * 4 + j3] * 0.5f);

    const float4* R = reinterpret_cast<const float4*>(g_px1)
                    + ((size_t)(dir * SP + 16 + s0) * B_ + bq) * 4 + j;
    float* H = g_h1 + (size_t)s0 * HROW + bq * 8 + dir * 4 + j;

    float h = 0.0f, c = 0.0f;
    float4 q[8];
#pragma unroll
    for (int k = 0; k < 8; ++k) q[k] = __ldg(R + SG * k * ROW);
    R += SG * 8 * ROW;

#pragma unroll 1
    for (int it = 0; it < S_; it += 8) {
#pragma unroll
        for (int k = 0; k < 8; ++k) {
            float4 p = q[k];
            q[k] = __ldg(R + SG * k * ROW);
            float hn1 = __shfl_sync(0xffffffffu, h, src1);
            float hn2 = __shfl_sync(0xffffffffu, h, src2);
            float hn3 = __shfl_sync(0xffffffffu, h, src3);
            float gi = fmaf(Wi.w,  hn3, fmaf(Wi.z,  hn2, fmaf(Wi.y,  hn1, fmaf(Wi.x,  h, p.x))));
            float gf = fmaf(Wff.w, hn3, fmaf(Wff.z, hn2, fmaf(Wff.y, hn1, fmaf(Wff.x, h, p.y))));
            float gg = fmaf(Wg.w,  hn3, fmaf(Wg.z,  hn2, fmaf(Wg.y,  hn1, fmaf(Wg.x,  h, p.z))));
            float go = fmaf(Wo.w,  hn3, fmaf(Wo.z,  hn2, fmaf(Wo.y,  hn1, fmaf(Wo.x,  h, p.w))));
            gi = sigm_pre(gi); gf = sigm_pre(gf); gg = tanha(gg); go = sigm_pre(go);
            c = fmaf(gf, c, gi * gg);
            h = go * tanha(c);
            H[SG * k * HROW] = h;
        }
        R += SG * 8 * ROW;
        H += SG * 8 * HROW;
    }
}

__global__ __launch_bounds__(32) void k_rec1(
    const float* __restrict__ Whh_f, const float* __restrict__ Whh_b)
{
    if (blockIdx.x < 32) rec1_dir<1>(Whh_f, threadIdx.x);
    else                 rec1_dir<-1>(Whh_b, threadIdx.x);
}

// ---------------- kernel C: layer-2 input projection ------------------------
__global__ __launch_bounds__(256) void k_px2(
    const float* __restrict__ Wih_f, const float* __restrict__ bih_f, const float* __restrict__ bhh_f,
    const float* __restrict__ Wih_b, const float* __restrict__ bih_b, const float* __restrict__ bhh_b)
{
    __shared__ float Ws[2 * 8 * 8];
    __shared__ float bs[2 * 8];
    int t = threadIdx.x;
    if (t < 64) {
        int row = t >> 3;                       // 0..7 : i0,i1,f0,f1,g0,g1,o0,o1
        float sc = (row == 4 || row == 5) ? 1.0f : 0.5f;
        Ws[t] = Wih_f[t] * sc; Ws[64 + t] = Wih_b[t] * sc;
    }
    if (t < 8) {
        float sc = (t == 4 || t == 5) ? 1.0f : 0.5f;
        bs[t] = (bih_f[t] + bhh_f[t]) * sc; bs[8 + t] = (bih_b[t] + bhh_b[t]) * sc;
    }
    __syncthreads();

    int p = blockIdx.x * 256 + t;                  // p = s*B + b
    int s = p >> 8;
    int b = p & (B_ - 1);
    float hr[8];
    const float4* hp = reinterpret_cast<const float4*>(g_h1) + (size_t)p * 2;
    float4 v0 = hp[0], v1 = hp[1];
    hr[0] = v0.x; hr[1] = v0.y; hr[2] = v0.z; hr[3] = v0.w;
    hr[4] = v1.x; hr[5] = v1.y; hr[6] = v1.z; hr[7] = v1.w;

#pragma unroll
    for (int dir = 0; dir < 2; ++dir) {
        float acc[8];
#pragma unroll
        for (int g = 0; g < 8; ++g) {
            float a = bs[dir * 8 + g];
            const float* wr = Ws + dir * 64 + g * 8;
#pragma unroll
            for (int f = 0; f < 8; ++f) a = fmaf(hr[f], wr[f], a);
            acc[g] = a;
        }
        float4* o = reinterpret_cast<float4*>(g_px2)
                  + ((size_t)(dir * SP + 16 + s) * B_ + b) * 2;
        o[0] = make_float4(acc[0], acc[2], acc[4], acc[6]);   // (i0,f0,g0,o0)
        o[1] = make_float4(acc[1], acc[3], acc[5], acc[7]);   // (i1,f1,g1,o1)
    }
}

// ---------------- kernel D: layer-2 recurrence (redundant state, no shfl) --
template <int SG>
__device__ __forceinline__ void rec2_dir(const float* __restrict__ Whh,
                                         float* __restrict__ out, int lane)
{
    constexpr int ROW = B_ * 2;            // px2 row stride in float4
    const int dir = (SG < 0);
    const int s0  = (SG < 0) ? (S_ - 1) : 0;

    int b = (blockIdx.x & 15) * 16 + lane;

    float4 wi = make_float4(Whh[0]  * 0.5f, Whh[1]  * 0.5f, Whh[2]  * 0.5f, Whh[3]  * 0.5f);
    float4 wf = make_float4(Whh[4]  * 0.5f, Whh[5]  * 0.5f, Whh[6]  * 0.5f, Whh[7]  * 0.5f);
    float4 wg = make_float4(Whh[8],         Whh[9],         Whh[10],        Whh[11]);
    float4 wo = make_float4(Whh[12] * 0.5f, Whh[13] * 0.5f, Whh[14] * 0.5f, Whh[15] * 0.5f);

    const float4* R = reinterpret_cast<const float4*>(g_px2)
                    + ((size_t)(dir * SP + 16 + s0) * B_ + b) * 2;
    float* O = out + (size_t)b * S_ * 4 + (size_t)s0 * 4 + dir * 2;

    float h0 = 0.0f, h1 = 0.0f, c0 = 0.0f, c1 = 0.0f;
    float4 qa[8], qb[8];
#pragma unroll
    for (int k = 0; k < 8; ++k) {
        qa[k] = __ldg(R + SG * k * ROW);
        qb[k] = __ldg(R + SG * k * ROW + 1);
    }
    R += SG * 8 * ROW;

#pragma unroll 1
    for (int it = 0; it < S_; it += 8) {
#pragma unroll
        for (int k = 0; k < 8; ++k) {
            float4 pa = qa[k], pb = qb[k];
            qa[k] = __ldg(R + SG * k * ROW);
            qb[k] = __ldg(R + SG * k * ROW + 1);
            float i0 = sigm_pre(fmaf(wi.y, h1, fmaf(wi.x, h0, pa.x)));
            float f0 = sigm_pre(fmaf(wf.y, h1, fmaf(wf.x, h0, pa.y)));
            float g0 = tanha   (fmaf(wg.y, h1, fmaf(wg.x, h0, pa.z)));
            float o0 = sigm_pre(fmaf(wo.y, h1, fmaf(wo.x, h0, pa.w)));
            float i1 = sigm_pre(fmaf(wi.w, h1, fmaf(wi.z, h0, pb.x)));
            float f1 = sigm_pre(fmaf(wf.w, h1, fmaf(wf.z, h0, pb.y)));
            float g1 = tanha   (fmaf(wg.w, h1, fmaf(wg.z, h0, pb.z)));
            float o1 = sigm_pre(fmaf(wo.w, h1, fmaf(wo.z, h0, pb.w)));
            c0 = fmaf(f0, c0, i0 * g0);
            c1 = fmaf(f1, c1, i1 * g1);
            h0 = o0 * tanha(c0);
            h1 = o1 * tanha(c1);
            *reinterpret_cast<float2*>(O + SG * k * 4) = make_float2(h0, h1);
        }
        R += SG * 8 * ROW;
        O += SG * 32;
    }
}

__global__ __launch_bounds__(16) void k_rec2(
    const float* __restrict__ Whh_f, const float* __restrict__ Whh_b,
    float* __restrict__ out)
{
    if (blockIdx.x < 16) rec2_dir<1>(Whh_f, out, threadIdx.x);
    else                 rec2_dir<-1>(Whh_b, out, threadIdx.x);
}

// ---------------- launch ----------------------------------------------------
extern "C" void kernel_launch(void* const* d_in, const int* in_sizes, int n_in,
                              void* d_out, int out_size)
{
    const float* x       = (const float*)d_in[0];
    const float* l1Wih_f = (const float*)d_in[1];
    const float* l1Whh_f = (const float*)d_in[2];
    const float* l1bih_f = (const float*)d_in[3];
    const float* l1bhh_f = (const float*)d_in[4];
    const float* l1Wih_b = (const float*)d_in[5];
    const float* l1Whh_b = (const float*)d_in[6];
    const float* l1bih_b = (const float*)d_in[7];
    const float* l1bhh_b = (const float*)d_in[8];
    const float* l2Wih_f = (const float*)d_in[9];
    const float* l2Whh_f = (const float*)d_in[10];
    const float* l2bih_f = (const float*)d_in[11];
    const float* l2bhh_f = (const float*)d_in[12];
    const float* l2Wih_b = (const float*)d_in[13];
    const float* l2Whh_b = (const float*)d_in[14];
    const float* l2bih_b = (const float*)d_in[15];
    const float* l2bhh_b = (const float*)d_in[16];

    k_px1<<<NP / 256, 256>>>(x, l1Wih_f, l1bih_f, l1bhh_f, l1Wih_b, l1bih_b, l1bhh_b);
    k_rec1<<<64, 32>>>(l1Whh_f, l1Whh_b);
    k_px2<<<NP / 256, 256>>>(l2Wih_f, l2bih_f, l2bhh_f, l2Wih_b, l2bih_b, l2bhh_b);
    k_rec2<<<32, 16>>>(l2Whh_f, l2Whh_b, (float*)d_out);
}

// round 5
// speedup vs baseline: 4.4772x; 2.7260x over previous
#include <cuda_runtime.h>

#define B_   256
#define S_   2048
#define F_   64
#define NP   (B_ * S_)
#define SP   (S_ + 32)          // padded rows (16 each side)

#define CH   256                // chunk length
#define WU   64                 // warm-up steps
#define NCH  (S_ / CH)          // 8 chunks

// ---------------- scratch (device globals; zero-init, no allocations) -----
__device__ float g_px1[2 * SP * B_ * 16];   // 68.2 MB
__device__ float g_h1[S_ * B_ * 8];         // 16.8 MB
__device__ float g_px2[2 * SP * B_ * 8];    // 34.1 MB

// ---------------- activations ----------------------------------------------
__device__ __forceinline__ float tanha(float x) {
    float r; asm("tanh.approx.f32 %0, %1;" : "=f"(r) : "f"(x)); return r;
}
__device__ __forceinline__ float sigm_pre(float y) {   // input pre-scaled by 0.5
    return fmaf(0.5f, tanha(y), 0.5f);
}

// ---------------- kernel A: layer-1 input projection ------------------------
__global__ __launch_bounds__(256) void k_px1(
    const float* __restrict__ x,
    const float* __restrict__ Wih_f, const float* __restrict__ bih_f, const float* __restrict__ bhh_f,
    const float* __restrict__ Wih_b, const float* __restrict__ bih_b, const float* __restrict__ bhh_b)
{
    __shared__ float Ws[2 * 16 * 64];
    __shared__ float bs[2 * 16];
    int t = threadIdx.x;
    for (int i = t; i < 16 * 64; i += 256) {
        int row = i >> 6;
        float sc = (row >= 8 && row < 12) ? 1.0f : 0.5f;
        Ws[i]        = Wih_f[i] * sc;
        Ws[1024 + i] = Wih_b[i] * sc;
    }
    if (t < 16) {
        float sc = (t >= 8 && t < 12) ? 1.0f : 0.5f;
        bs[t]      = (bih_f[t] + bhh_f[t]) * sc;
        bs[16 + t] = (bih_b[t] + bhh_b[t]) * sc;
    }
    __syncthreads();

    int p = blockIdx.x * 256 + t;          // p = b*S + s
    int b = p >> 11;
    int s = p & (S_ - 1);

    float xr[64];
    const float4* xp = reinterpret_cast<const float4*>(x) + (size_t)p * 16;
#pragma unroll
    for (int i = 0; i < 16; ++i) {
        float4 v = xp[i];
        xr[4 * i + 0] = v.x; xr[4 * i + 1] = v.y;
        xr[4 * i + 2] = v.z; xr[4 * i + 3] = v.w;
    }

#pragma unroll 1
    for (int dir = 0; dir < 2; ++dir) {
        float acc[16];
#pragma unroll
        for (int g = 0; g < 16; ++g) {
            float a = bs[dir * 16 + g];
            const float4* wr = reinterpret_cast<const float4*>(Ws + dir * 1024 + g * 64);
#pragma unroll
            for (int q = 0; q < 16; ++q) {
                float4 w = wr[q];
                a = fmaf(xr[4 * q + 0], w.x, a);
                a = fmaf(xr[4 * q + 1], w.y, a);
                a = fmaf(xr[4 * q + 2], w.z, a);
                a = fmaf(xr[4 * q + 3], w.w, a);
            }
            acc[g] = a;
        }
        float4* o = reinterpret_cast<float4*>(g_px1)
                  + ((size_t)(dir * SP + 16 + s) * B_ + b) * 4;
#pragma unroll
        for (int j = 0; j < 4; ++j)
            o[j] = make_float4(acc[j], acc[4 + j], acc[8 + j], acc[12 + j]);
    }
}

// ---------------- kernel B: layer-1 recurrence (chunked) --------------------
#define LSTM1_BODY(P)                                                              \
    {                                                                              \
        float hn1 = __shfl_sync(0xffffffffu, h, src1);                             \
        float hn2 = __shfl_sync(0xffffffffu, h, src2);                             \
        float hn3 = __shfl_sync(0xffffffffu, h, src3);                             \
        float gi = fmaf(Wi.w,  hn3, fmaf(Wi.z,  hn2, fmaf(Wi.y,  hn1, fmaf(Wi.x,  h, (P).x)))); \
        float gf = fmaf(Wff.w, hn3, fmaf(Wff.z, hn2, fmaf(Wff.y, hn1, fmaf(Wff.x, h, (P).y)))); \
        float gg = fmaf(Wg.w,  hn3, fmaf(Wg.z,  hn2, fmaf(Wg.y,  hn1, fmaf(Wg.x,  h, (P).z)))); \
        float go = fmaf(Wo.w,  hn3, fmaf(Wo.z,  hn2, fmaf(Wo.y,  hn1, fmaf(Wo.x,  h, (P).w)))); \
        gi = sigm_pre(gi); gf = sigm_pre(gf); gg = tanha(gg); go = sigm_pre(go);   \
        c = fmaf(gf, c, gi * gg);                                                  \
        h = go * tanha(c);                                                         \
    }

template <int SG>
__device__ __forceinline__ void rec1_dir(const float* __restrict__ Whh,
                                         int lane, int chunk, int bgroup)
{
    constexpr int ROW  = B_ * 4;           // px1 row stride in float4
    constexpr int HROW = B_ * 8;           // h1 row stride in floats
    const int dir = (SG < 0);

    int bq = bgroup * 8 + (lane >> 2);
    int j  = lane & 3;
    int lb = lane & ~3;
    int j1 = (j + 1) & 3, j2 = (j + 2) & 3, j3 = (j + 3) & 3;
    int src1 = lb + j1, src2 = lb + j2, src3 = lb + j3;

    float4 Wi  = make_float4(Whh[(0  + j) * 4 + j]  * 0.5f, Whh[(0  + j) * 4 + j1] * 0.5f,
                             Whh[(0  + j) * 4 + j2] * 0.5f, Whh[(0  + j) * 4 + j3] * 0.5f);
    float4 Wff = make_float4(Whh[(4  + j) * 4 + j]  * 0.5f, Whh[(4  + j) * 4 + j1] * 0.5f,
                             Whh[(4  + j) * 4 + j2] * 0.5f, Whh[(4  + j) * 4 + j3] * 0.5f);
    float4 Wg  = make_float4(Whh[(8  + j) * 4 + j],         Whh[(8  + j) * 4 + j1],
                             Whh[(8  + j) * 4 + j2],        Whh[(8  + j) * 4 + j3]);
    float4 Wo  = make_float4(Whh[(12 + j) * 4 + j]  * 0.5f, Whh[(12 + j) * 4 + j1] * 0.5f,
                             Whh[(12 + j) * 4 + j2] * 0.5f, Whh[(12 + j) * 4 + j3] * 0.5f);

    int cs = chunk * CH;
    int s_store0 = (SG > 0) ? cs : cs + CH - 1;                         // first stored step
    int s_begin  = (SG > 0) ? ((chunk == 0) ? 0 : cs - WU)
                            : ((chunk == NCH - 1) ? S_ - 1 : cs + CH - 1 + WU);
    int wu = (SG > 0) ? (cs - s_begin) : (s_begin - s_store0);          // 0 or WU

    const float4* R = reinterpret_cast<const float4*>(g_px1)
                    + ((size_t)(dir * SP + 16 + s_begin) * B_ + bq) * 4 + j;
    float* H = g_h1 + (size_t)s_store0 * HROW + bq * 8 + dir * 4 + j;

    float h = 0.0f, c = 0.0f;
    float4 q[8];
#pragma unroll
    for (int k = 0; k < 8; ++k) q[k] = __ldg(R + SG * k * ROW);
    R += SG * 8 * ROW;

#pragma unroll 1
    for (int it = 0; it < wu; it += 8) {            // warm-up: no stores
#pragma unroll
        for (int k = 0; k < 8; ++k) {
            float4 p = q[k];
            q[k] = __ldg(R + SG * k * ROW);
            LSTM1_BODY(p);
        }
        R += SG * 8 * ROW;
    }

#pragma unroll 1
    for (int it = 0; it < CH; it += 8) {            // main: with stores
#pragma unroll
        for (int k = 0; k < 8; ++k) {
            float4 p = q[k];
            q[k] = __ldg(R + SG * k * ROW);
            LSTM1_BODY(p);
            H[SG * k * HROW] = h;
        }
        R += SG * 8 * ROW;
        H += SG * 8 * HROW;
    }
}

__global__ __launch_bounds__(32) void k_rec1(
    const float* __restrict__ Whh_f, const float* __restrict__ Whh_b)
{
    int bx    = blockIdx.x;                 // [2][NCH][32]
    int rem   = bx & (NCH * 32 - 1);
    int chunk = rem >> 5;
    int bg    = rem & 31;
    if (bx < NCH * 32) rec1_dir<1>(Whh_f, threadIdx.x, chunk, bg);
    else               rec1_dir<-1>(Whh_b, threadIdx.x, chunk, bg);
}

// ---------------- kernel C: layer-2 input projection ------------------------
__global__ __launch_bounds__(256) void k_px2(
    const float* __restrict__ Wih_f, const float* __restrict__ bih_f, const float* __restrict__ bhh_f,
    const float* __restrict__ Wih_b, const float* __restrict__ bih_b, const float* __restrict__ bhh_b)
{
    __shared__ float Ws[2 * 8 * 8];
    __shared__ float bs[2 * 8];
    int t = threadIdx.x;
    if (t < 64) {
        int row = t >> 3;
        float sc = (row == 4 || row == 5) ? 1.0f : 0.5f;
        Ws[t] = Wih_f[t] * sc; Ws[64 + t] = Wih_b[t] * sc;
    }
    if (t < 8) {
        float sc = (t == 4 || t == 5) ? 1.0f : 0.5f;
        bs[t] = (bih_f[t] + bhh_f[t]) * sc; bs[8 + t] = (bih_b[t] + bhh_b[t]) * sc;
    }
    __syncthreads();

    int p = blockIdx.x * 256 + t;                  // p = s*B + b
    int s = p >> 8;
    int b = p & (B_ - 1);
    float hr[8];
    const float4* hp = reinterpret_cast<const float4*>(g_h1) + (size_t)p * 2;
    float4 v0 = hp[0], v1 = hp[1];
    hr[0] = v0.x; hr[1] = v0.y; hr[2] = v0.z; hr[3] = v0.w;
    hr[4] = v1.x; hr[5] = v1.y; hr[6] = v1.z; hr[7] = v1.w;

#pragma unroll
    for (int dir = 0; dir < 2; ++dir) {
        float acc[8];
#pragma unroll
        for (int g = 0; g < 8; ++g) {
            float a = bs[dir * 8 + g];
            const float* wr = Ws + dir * 64 + g * 8;
#pragma unroll
            for (int f = 0; f < 8; ++f) a = fmaf(hr[f], wr[f], a);
            acc[g] = a;
        }
        float4* o = reinterpret_cast<float4*>(g_px2)
                  + ((size_t)(dir * SP + 16 + s) * B_ + b) * 2;
        o[0] = make_float4(acc[0], acc[2], acc[4], acc[6]);
        o[1] = make_float4(acc[1], acc[3], acc[5], acc[7]);
    }
}

// ---------------- kernel D: layer-2 recurrence (chunked, redundant state) --
#define LSTM2_BODY(PA, PB)                                                         \
    {                                                                              \
        float i0 = sigm_pre(fmaf(wi.y, h1, fmaf(wi.x, h0, (PA).x)));               \
        float f0 = sigm_pre(fmaf(wf.y, h1, fmaf(wf.x, h0, (PA).y)));               \
        float g0 = tanha   (fmaf(wg.y, h1, fmaf(wg.x, h0, (PA).z)));               \
        float o0 = sigm_pre(fmaf(wo.y, h1, fmaf(wo.x, h0, (PA).w)));               \
        float i1 = sigm_pre(fmaf(wi.w, h1, fmaf(wi.z, h0, (PB).x)));               \
        float f1 = sigm_pre(fmaf(wf.w, h1, fmaf(wf.z, h0, (PB).y)));               \
        float g1 = tanha   (fmaf(wg.w, h1, fmaf(wg.z, h0, (PB).z)));               \
        float o1 = sigm_pre(fmaf(wo.w, h1, fmaf(wo.z, h0, (PB).w)));               \
        c0 = fmaf(f0, c0, i0 * g0);                                                \
        c1 = fmaf(f1, c1, i1 * g1);                                                \
        h0 = o0 * tanha(c0);                                                       \
        h1 = o1 * tanha(c1);                                                       \
    }

template <int SG>
__device__ __forceinline__ void rec2_dir(const float* __restrict__ Whh,
                                         float* __restrict__ out,
                                         int lane, int chunk, int bgroup)
{
    constexpr int ROW = B_ * 2;            // px2 row stride in float4
    const int dir = (SG < 0);

    int b = bgroup * 16 + lane;

    float4 wi = make_float4(Whh[0]  * 0.5f, Whh[1]  * 0.5f, Whh[2]  * 0.5f, Whh[3]  * 0.5f);
    float4 wf = make_float4(Whh[4]  * 0.5f, Whh[5]  * 0.5f, Whh[6]  * 0.5f, Whh[7]  * 0.5f);
    float4 wg = make_float4(Whh[8],         Whh[9],         Whh[10],        Whh[11]);
    float4 wo = make_float4(Whh[12] * 0.5f, Whh[13] * 0.5f, Whh[14] * 0.5f, Whh[15] * 0.5f);

    int cs = chunk * CH;
    int s_store0 = (SG > 0) ? cs : cs + CH - 1;
    int s_begin  = (SG > 0) ? ((chunk == 0) ? 0 : cs - WU)
                            : ((chunk == NCH - 1) ? S_ - 1 : cs + CH - 1 + WU);
    int wu = (SG > 0) ? (cs - s_begin) : (s_begin - s_store0);

    const float4* R = reinterpret_cast<const float4*>(g_px2)
                    + ((size_t)(dir * SP + 16 + s_begin) * B_ + b) * 2;
    float* O = out + (size_t)b * S_ * 4 + (size_t)s_store0 * 4 + dir * 2;

    float h0 = 0.0f, h1 = 0.0f, c0 = 0.0f, c1 = 0.0f;
    float4 qa[8], qb[8];
#pragma unroll
    for (int k = 0; k < 8; ++k) {
        qa[k] = __ldg(R + SG * k * ROW);
        qb[k] = __ldg(R + SG * k * ROW + 1);
    }
    R += SG * 8 * ROW;

#pragma unroll 1
    for (int it = 0; it < wu; it += 8) {            // warm-up
#pragma unroll
        for (int k = 0; k < 8; ++k) {
            float4 pa = qa[k], pb = qb[k];
            qa[k] = __ldg(R + SG * k * ROW);
            qb[k] = __ldg(R + SG * k * ROW + 1);
            LSTM2_BODY(pa, pb);
        }
        R += SG * 8 * ROW;
    }

#pragma unroll 1
    for (int it = 0; it < CH; it += 8) {            // main
#pragma unroll
        for (int k = 0; k < 8; ++k) {
            float4 pa = qa[k], pb = qb[k];
            qa[k] = __ldg(R + SG * k * ROW);
            qb[k] = __ldg(R + SG * k * ROW + 1);
            LSTM2_BODY(pa, pb);
            *reinterpret_cast<float2*>(O + SG * k * 4) = make_float2(h0, h1);
        }
        R += SG * 8 * ROW;
        O += SG * 32;
    }
}

__global__ __launch_bounds__(16) void k_rec2(
    const float* __restrict__ Whh_f, const float* __restrict__ Whh_b,
    float* __restrict__ out)
{
    int bx    = blockIdx.x;                 // [2][NCH][16]
    int rem   = bx & (NCH * 16 - 1);
    int chunk = rem >> 4;
    int bg    = rem & 15;
    if (bx < NCH * 16) rec2_dir<1>(Whh_f, out, threadIdx.x, chunk, bg);
    else               rec2_dir<-1>(Whh_b, out, threadIdx.x, chunk, bg);
}

// ---------------- launch ----------------------------------------------------
extern "C" void kernel_launch(void* const* d_in, const int* in_sizes, int n_in,
                              void* d_out, int out_size)
{
    const float* x       = (const float*)d_in[0];
    const float* l1Wih_f = (const float*)d_in[1];
    const float* l1Whh_f = (const float*)d_in[2];
    const float* l1bih_f = (const float*)d_in[3];
    const float* l1bhh_f = (const float*)d_in[4];
    const float* l1Wih_b = (const float*)d_in[5];
    const float* l1Whh_b = (const float*)d_in[6];
    const float* l1bih_b = (const float*)d_in[7];
    const float* l1bhh_b = (const float*)d_in[8];
    const float* l2Wih_f = (const float*)d_in[9];
    const float* l2Whh_f = (const float*)d_in[10];
    const float* l2bih_f = (const float*)d_in[11];
    const float* l2bhh_f = (const float*)d_in[12];
    const float* l2Wih_b = (const float*)d_in[13];
    const float* l2Whh_b = (const float*)d_in[14];
    const float* l2bih_b = (const float*)d_in[15];
    const float* l2bhh_b = (const float*)d_in[16];

    k_px1<<<NP / 256, 256>>>(x, l1Wih_f, l1bih_f, l1bhh_f, l1Wih_b, l1bih_b, l1bhh_b);
    k_rec1<<<2 * NCH * 32, 32>>>(l1Whh_f, l1Whh_b);
    k_px2<<<NP / 256, 256>>>(l2Wih_f, l2bih_f, l2bhh_f, l2Wih_b, l2bih_b, l2bhh_b);
    k_rec2<<<2 * NCH * 16, 16>>>(l2Whh_f, l2Whh_b, (float*)d_out);
}

// round 7
// speedup vs baseline: 5.5800x; 1.2463x over previous
#include <cuda_runtime.h>

#define B_   256
#define S_   2048
#define F_   64
#define NP   (B_ * S_)
#define SP   (S_ + 32)          // padded rows (16 each side)

#define CH   64                 // chunk length
#define WU   64                 // warm-up steps
#define NCH  (S_ / CH)          // 32 chunks

// ---------------- scratch (device globals; no allocations) ----------------
__device__ float g_px1[2 * SP * B_ * 16];   // 68.2 MB
__device__ float g_h1[S_ * B_ * 8];         // 16.8 MB
__device__ float g_px2[2 * SP * B_ * 8];    // 34.1 MB

// ---------------- activations ----------------------------------------------
__device__ __forceinline__ float tanha(float x) {
    float r; asm("tanh.approx.f32 %0, %1;" : "=f"(r) : "f"(x)); return r;
}
__device__ __forceinline__ float sigm_pre(float y) {   // input pre-scaled by 0.5
    return fmaf(0.5f, tanha(y), 0.5f);
}

// ---------------- packed f32x2 helpers --------------------------------------
__device__ __forceinline__ void ffma2(unsigned long long& d, unsigned long long a,
                                      unsigned long long b, unsigned long long c) {
    asm("fma.rn.f32x2 %0, %1, %2, %3;" : "=l"(d) : "l"(a), "l"(b), "l"(c));
}
__device__ __forceinline__ unsigned long long pack2(float lo, float hi) {
    unsigned long long r; asm("mov.b64 %0, {%1,%2};" : "=l"(r) : "f"(lo), "f"(hi)); return r;
}
__device__ __forceinline__ float2 unpack2(unsigned long long v) {
    float lo, hi; asm("mov.b64 {%0,%1}, %2;" : "=f"(lo), "=f"(hi) : "l"(v));
    return make_float2(lo, hi);
}

// ---------------- kernel A: layer-1 input projection (FFMA2) ----------------
__global__ __launch_bounds__(256) void k_px1(
    const float* __restrict__ x,
    const float* __restrict__ Wih_f, const float* __restrict__ bih_f, const float* __restrict__ bhh_f,
    const float* __restrict__ Wih_b, const float* __restrict__ bih_b, const float* __restrict__ bhh_b)
{
    __shared__ __align__(16) float Ws[2 * 16 * 64];
    __shared__ float bs[2 * 16];
    int t = threadIdx.x;
    for (int i = t; i < 16 * 64; i += 256) {
        int row = i >> 6;
        float sc = (row >= 8 && row < 12) ? 1.0f : 0.5f;
        Ws[i]        = Wih_f[i] * sc;
        Ws[1024 + i] = Wih_b[i] * sc;
    }
    if (t < 16) {
        float sc = (t >= 8 && t < 12) ? 1.0f : 0.5f;
        bs[t]      = (bih_f[t] + bhh_f[t]) * sc;
        bs[16 + t] = (bih_b[t] + bhh_b[t]) * sc;
    }
    __syncthreads();

    int p = blockIdx.x * 256 + t;          // p = b*S + s
    int b = p >> 11;
    int s = p & (S_ - 1);

    // x pairs straight from memory as 64-bit lanes: 64 floats = 16 ulonglong2
    unsigned long long x2[32];
    const ulonglong2* xp = reinterpret_cast<const ulonglong2*>(x) + (size_t)p * 16;
#pragma unroll
    for (int i = 0; i < 16; ++i) {
        ulonglong2 v = xp[i];
        x2[2 * i + 0] = v.x;
        x2[2 * i + 1] = v.y;
    }

#pragma unroll 1
    for (int dir = 0; dir < 2; ++dir) {
        float acc[16];
#pragma unroll
        for (int g = 0; g < 16; ++g) {
            unsigned long long a2 = pack2(bs[dir * 16 + g], 0.0f);
            const unsigned long long* w2 =
                reinterpret_cast<const unsigned long long*>(Ws + dir * 1024 + g * 64);
#pragma unroll
            for (int q = 0; q < 32; ++q) ffma2(a2, x2[q], w2[q], a2);
            float2 u = unpack2(a2);
            acc[g] = u.x + u.y;
        }
        float4* o = reinterpret_cast<float4*>(g_px1)
                  + ((size_t)(dir * SP + 16 + s) * B_ + b) * 4;
#pragma unroll
        for (int j = 0; j < 4; ++j)
            o[j] = make_float4(acc[j], acc[4 + j], acc[8 + j], acc[12 + j]);
    }
}

// ---------------- kernel B: layer-1 recurrence (chunked) --------------------
#define LSTM1_BODY(P)                                                              \
    {                                                                              \
        float hn1 = __shfl_sync(0xffffffffu, h, src1);                             \
        float hn2 = __shfl_sync(0xffffffffu, h, src2);                             \
        float hn3 = __shfl_sync(0xffffffffu, h, src3);                             \
        float gi = fmaf(Wi.w,  hn3, fmaf(Wi.z,  hn2, fmaf(Wi.y,  hn1, fmaf(Wi.x,  h, (P).x)))); \
        float gf = fmaf(Wff.w, hn3, fmaf(Wff.z, hn2, fmaf(Wff.y, hn1, fmaf(Wff.x, h, (P).y)))); \
        float gg = fmaf(Wg.w,  hn3, fmaf(Wg.z,  hn2, fmaf(Wg.y,  hn1, fmaf(Wg.x,  h, (P).z)))); \
        float go = fmaf(Wo.w,  hn3, fmaf(Wo.z,  hn2, fmaf(Wo.y,  hn1, fmaf(Wo.x,  h, (P).w)))); \
        gi = sigm_pre(gi); gf = sigm_pre(gf); gg = tanha(gg); go = sigm_pre(go);   \
        c = fmaf(gf, c, gi * gg);                                                  \
        h = go * tanha(c);                                                         \
    }

template <int SG>
__device__ __forceinline__ void rec1_dir(const float* __restrict__ Whh,
                                         int lane, int chunk, int bgroup)
{
    constexpr int ROW  = B_ * 4;           // px1 row stride in float4
    constexpr int HROW = B_ * 8;           // h1 row stride in floats
    const int dir = (SG < 0);

    int bq = bgroup * 8 + (lane >> 2);
    int j  = lane & 3;
    int lb = lane & ~3;
    int j1 = (j + 1) & 3, j2 = (j + 2) & 3, j3 = (j + 3) & 3;
    int src1 = lb + j1, src2 = lb + j2, src3 = lb + j3;

    float4 Wi  = make_float4(Whh[(0  + j) * 4 + j]  * 0.5f, Whh[(0  + j) * 4 + j1] * 0.5f,
                             Whh[(0  + j) * 4 + j2] * 0.5f, Whh[(0  + j) * 4 + j3] * 0.5f);
    float4 Wff = make_float4(Whh[(4  + j) * 4 + j]  * 0.5f, Whh[(4  + j) * 4 + j1] * 0.5f,
                             Whh[(4  + j) * 4 + j2] * 0.5f, Whh[(4  + j) * 4 + j3] * 0.5f);
    float4 Wg  = make_float4(Whh[(8  + j) * 4 + j],         Whh[(8  + j) * 4 + j1],
                             Whh[(8  + j) * 4 + j2],        Whh[(8  + j) * 4 + j3]);
    float4 Wo  = make_float4(Whh[(12 + j) * 4 + j]  * 0.5f, Whh[(12 + j) * 4 + j1] * 0.5f,
                             Whh[(12 + j) * 4 + j2] * 0.5f, Whh[(12 + j) * 4 + j3] * 0.5f);

    int cs = chunk * CH;
    int s_store0 = (SG > 0) ? cs : cs + CH - 1;
    int s_begin  = (SG > 0) ? ((chunk == 0) ? 0 : cs - WU)
                            : ((chunk == NCH - 1) ? S_ - 1 : cs + CH - 1 + WU);
    int wu = (SG > 0) ? (cs - s_begin) : (s_begin - s_store0);      // 0 or WU

    const float4* R = reinterpret_cast<const float4*>(g_px1)
                    + ((size_t)(dir * SP + 16 + s_begin) * B_ + bq) * 4 + j;
    float* H = g_h1 + (size_t)s_store0 * HROW + bq * 8 + dir * 4 + j;

    float h = 0.0f, c = 0.0f;
    float4 q[8];
#pragma unroll
    for (int k = 0; k < 8; ++k) q[k] = __ldg(R + SG * k * ROW);
    R += SG * 8 * ROW;

#pragma unroll 1
    for (int it = 0; it < wu; it += 8) {            // warm-up: no stores
#pragma unroll
        for (int k = 0; k < 8; ++k) {
            float4 p = q[k];
            q[k] = __ldg(R + SG * k * ROW);
            LSTM1_BODY(p);
        }
        R += SG * 8 * ROW;
    }

#pragma unroll 1
    for (int it = 0; it < CH; it += 8) {            // main: with stores
#pragma unroll
        for (int k = 0; k < 8; ++k) {
            float4 p = q[k];
            q[k] = __ldg(R + SG * k * ROW);
            LSTM1_BODY(p);
            H[SG * k * HROW] = h;
        }
        R += SG * 8 * ROW;
        H += SG * 8 * HROW;
    }
}

__global__ __launch_bounds__(32) void k_rec1(
    const float* __restrict__ Whh_f, const float* __restrict__ Whh_b)
{
    int bx    = blockIdx.x;                 // [2][NCH][32]
    int rem   = bx & (NCH * 32 - 1);
    int chunk = rem >> 5;
    int bg    = rem & 31;
    if (bx < NCH * 32) rec1_dir<1>(Whh_f, threadIdx.x, chunk, bg);
    else               rec1_dir<-1>(Whh_b, threadIdx.x, chunk, bg);
}

// ---------------- kernel C: layer-2 input projection ------------------------
__global__ __launch_bounds__(256) void k_px2(
    const float* __restrict__ Wih_f, const float* __restrict__ bih_f, const float* __restrict__ bhh_f,
    const float* __restrict__ Wih_b, const float* __restrict__ bih_b, const float* __restrict__ bhh_b)
{
    __shared__ float Ws[2 * 8 * 8];
    __shared__ float bs[2 * 8];
    int t = threadIdx.x;
    if (t < 64) {
        int row = t >> 3;
        float sc = (row == 4 || row == 5) ? 1.0f : 0.5f;
        Ws[t] = Wih_f[t] * sc; Ws[64 + t] = Wih_b[t] * sc;
    }
    if (t < 8) {
        float sc = (t == 4 || t == 5) ? 1.0f : 0.5f;
        bs[t] = (bih_f[t] + bhh_f[t]) * sc; bs[8 + t] = (bih_b[t] + bhh_b[t]) * sc;
    }
    __syncthreads();

    int p = blockIdx.x * 256 + t;                  // p = s*B + b
    int s = p >> 8;
    int b = p & (B_ - 1);
    float hr[8];
    const float4* hp = reinterpret_cast<const float4*>(g_h1) + (size_t)p * 2;
    float4 v0 = hp[0], v1 = hp[1];
    hr[0] = v0.x; hr[1] = v0.y; hr[2] = v0.z; hr[3] = v0.w;
    hr[4] = v1.x; hr[5] = v1.y; hr[6] = v1.z; hr[7] = v1.w;

#pragma unroll
    for (int dir = 0; dir < 2; ++dir) {
        float acc[8];
#pragma unroll
        for (int g = 0; g < 8; ++g) {
            float a = bs[dir * 8 + g];
            const float* wr = Ws + dir * 64 + g * 8;
#pragma unroll
            for (int f = 0; f < 8; ++f) a = fmaf(hr[f], wr[f], a);
            acc[g] = a;
        }
        float4* o = reinterpret_cast<float4*>(g_px2)
                  + ((size_t)(dir * SP + 16 + s) * B_ + b) * 2;
        o[0] = make_float4(acc[0], acc[2], acc[4], acc[6]);
        o[1] = make_float4(acc[1], acc[3], acc[5], acc[7]);
    }
}

// ---------------- kernel D: layer-2 recurrence (chunked, full warps) -------
#define LSTM2_BODY(PA, PB)                                                         \
    {                                                                              \
        float i0 = sigm_pre(fmaf(wi.y, h1, fmaf(wi.x, h0, (PA).x)));               \
        float f0 = sigm_pre(fmaf(wf.y, h1, fmaf(wf.x, h0, (PA).y)));               \
        float g0 = tanha   (fmaf(wg.y, h1, fmaf(wg.x, h0, (PA).z)));               \
        float o0 = sigm_pre(fmaf(wo.y, h1, fmaf(wo.x, h0, (PA).w)));               \
        float i1 = sigm_pre(fmaf(wi.w, h1, fmaf(wi.z, h0, (PB).x)));               \
        float f1 = sigm_pre(fmaf(wf.w, h1, fmaf(wf.z, h0, (PB).y)));               \
        float g1 = tanha   (fmaf(wg.w, h1, fmaf(wg.z, h0, (PB).z)));               \
        float o1 = sigm_pre(fmaf(wo.w, h1, fmaf(wo.z, h0, (PB).w)));               \
        c0 = fmaf(f0, c0, i0 * g0);                                                \
        c1 = fmaf(f1, c1, i1 * g1);                                                \
        h0 = o0 * tanha(c0);                                                       \
        h1 = o1 * tanha(c1);                                                       \
    }

template <int SG>
__device__ __forceinline__ void rec2_dir(const float* __restrict__ Whh,
                                         float* __restrict__ out,
                                         int lane, int chunk, int bgroup)
{
    constexpr int ROW = B_ * 2;            // px2 row stride in float4
    const int dir = (SG < 0);

    int b = bgroup * 32 + lane;

    float4 wi = make_float4(Whh[0]  * 0.5f, Whh[1]  * 0.5f, Whh[2]  * 0.5f, Whh[3]  * 0.5f);
    float4 wf = make_float4(Whh[4]  * 0.5f, Whh[5]  * 0.5f, Whh[6]  * 0.5f, Whh[7]  * 0.5f);
    float4 wg = make_float4(Whh[8],         Whh[9],         Whh[10],        Whh[11]);
    float4 wo = make_float4(Whh[12] * 0.5f, Whh[13] * 0.5f, Whh[14] * 0.5f, Whh[15] * 0.5f);

    int cs = chunk * CH;
    int s_store0 = (SG > 0) ? cs : cs + CH - 1;
    int s_begin  = (SG > 0) ? ((chunk == 0) ? 0 : cs - WU)
                            : ((chunk == NCH - 1) ? S_ - 1 : cs + CH - 1 + WU);
    int wu = (SG > 0) ? (cs - s_begin) : (s_begin - s_store0);

    const float4* R = reinterpret_cast<const float4*>(g_px2)
                    + ((size_t)(dir * SP + 16 + s_begin) * B_ + b) * 2;
    float* O = out + (size_t)b * S_ * 4 + (size_t)s_store0 * 4 + dir * 2;

    float h0 = 0.0f, h1 = 0.0f, c0 = 0.0f, c1 = 0.0f;
    float4 qa[8], qb[8];
#pragma unroll
    for (int k = 0; k < 8; ++k) {
        qa[k] = __ldg(R + SG * k * ROW);
        qb[k] = __ldg(R + SG * k * ROW + 1);
    }
    R += SG * 8 * ROW;

#pragma unroll 1
    for (int it = 0; it < wu; it += 8) {            // warm-up
#pragma unroll
        for (int k = 0; k < 8; ++k) {
            float4 pa = qa[k], pb = qb[k];
            qa[k] = __ldg(R + SG * k * ROW);
            qb[k] = __ldg(R + SG * k * ROW + 1);
            LSTM2_BODY(pa, pb);
        }
        R += SG * 8 * ROW;
    }

#pragma unroll 1
    for (int it = 0; it < CH; it += 8) {            // main
#pragma unroll
        for (int k = 0; k < 8; ++k) {
            float4 pa = qa[k], pb = qb[k];
            qa[k] = __ldg(R + SG * k * ROW);
            qb[k] = __ldg(R + SG * k * ROW + 1);
            LSTM2_BODY(pa, pb);
            *reinterpret_cast<float2*>(O + SG * k * 4) = make_float2(h0, h1);
        }
        R += SG * 8 * ROW;
        O += SG * 32;
    }
}

__global__ __launch_bounds__(32) void k_rec2(
    const float* __restrict__ Whh_f, const float* __restrict__ Whh_b,
    float* __restrict__ out)
{
    int bx    = blockIdx.x;                 // [2][NCH][8]
    int rem   = bx & (NCH * 8 - 1);
    int chunk = rem >> 3;
    int bg    = rem & 7;
    if (bx < NCH * 8) rec2_dir<1>(Whh_f, out, threadIdx.x, chunk, bg);
    else              rec2_dir<-1>(Whh_b, out, threadIdx.x, chunk, bg);
}

// ---------------- launch ----------------------------------------------------
extern "C" void kernel_launch(void* const* d_in, const int* in_sizes, int n_in,
                              void* d_out, int out_size)
{
    const float* x       = (const float*)d_in[0];
    const float* l1Wih_f = (const float*)d_in[1];
    const float* l1Whh_f = (const float*)d_in[2];
    const float* l1bih_f = (const float*)d_in[3];
    const float* l1bhh_f = (const float*)d_in[4];
    const float* l1Wih_b = (const float*)d_in[5];
    const float* l1Whh_b = (const float*)d_in[6];
    const float* l1bih_b = (const float*)d_in[7];
    const float* l1bhh_b = (const float*)d_in[8];
    const float* l2Wih_f = (const float*)d_in[9];
    const float* l2Whh_f = (const float*)d_in[10];
    const float* l2bih_f = (const float*)d_in[11];
    const float* l2bhh_f = (const float*)d_in[12];
    const float* l2Wih_b = (const float*)d_in[13];
    const float* l2Whh_b = (const float*)d_in[14];
    const float* l2bih_b = (const float*)d_in[15];
    const float* l2bhh_b = (const float*)d_in[16];

    k_px1<<<NP / 256, 256>>>(x, l1Wih_f, l1bih_f, l1bhh_f, l1Wih_b, l1bih_b, l1bhh_b);
    k_rec1<<<2 * NCH * 32, 32>>>(l1Whh_f, l1Whh_b);
    k_px2<<<NP / 256, 256>>>(l2Wih_f, l2bih_f, l2bhh_f, l2Wih_b, l2bih_b, l2bhh_b);
    k_rec2<<<2 * NCH * 8, 32>>>(l2Whh_f, l2Whh_b, (float*)d_out);
}